// round 4
// baseline (speedup 1.0000x reference)
#include <cuda_runtime.h>
#include <math.h>

#define NH   12
#define NN   4096
#define ND   128
#define NIN  256

typedef unsigned long long u64t;

// ---- packed f32x2 helpers (FFMA2 path — only reachable via PTX) ----
__device__ __forceinline__ u64t pk2(float lo, float hi) {
    u64t r;
    asm("mov.b64 %0, {%1, %2};" : "=l"(r) : "f"(lo), "f"(hi));
    return r;
}
__device__ __forceinline__ void upk2(u64t v, float& lo, float& hi) {
    asm("mov.b64 {%0, %1}, %2;" : "=f"(lo), "=f"(hi) : "l"(v));
}
__device__ __forceinline__ void fma2(u64t& d, u64t a, u64t b) {
    asm("fma.rn.f32x2 %0, %1, %2, %0;" : "+l"(d) : "l"(a), "l"(b));
}
__device__ __forceinline__ void mul2(u64t& d, u64t a) {
    asm("mul.rn.f32x2 %0, %0, %1;" : "+l"(d) : "l"(a));
}

// ---------------- scratch (static device globals; no allocation) ----------------
__device__ float g_QS[NH * NN * ND];
__device__ float g_KS[NH * NN * ND];
__device__ float g_VS[NH * NN * ND];
__device__ float g_QT[NH * NN];
__device__ float g_KT[NH * NN];
__device__ float g_VT[NH * NN];
__device__ float g_OS[NH * NN * ND];
__device__ float g_OT[NH * NN];

// =====================================================================
// Kernel 1: hyperbolic linear projections (unchanged from R1)
// =====================================================================
__global__ __launch_bounds__(256) void proj_kernel(
    const float* __restrict__ x,
    const float* __restrict__ Wq, const float* __restrict__ bq,
    const float* __restrict__ Wk, const float* __restrict__ bk,
    const float* __restrict__ Wv, const float* __restrict__ bv)
{
    const int by  = blockIdx.y;
    const int h   = by % NH;
    const int sel = by / NH;

    const float* W = (sel == 0) ? Wq : (sel == 1) ? Wk : Wv;
    const float* B = (sel == 0) ? bq : (sel == 1) ? bk : bv;
    float* outS    = (sel == 0) ? g_QS : (sel == 1) ? g_KS : g_VS;
    float* outT    = (sel == 0) ? g_QT : (sel == 1) ? g_KT : g_VT;

    const int n0  = blockIdx.x * 64;
    const int tid = threadIdx.x;
    const int tx  = tid & 15;
    const int ty  = tid >> 4;

    __shared__ float Xt[32][68];
    __shared__ float Wt[32][132];

    // diagonal-packed accumulators: rows pairs (2) x col pairs (4) x {d1,d2}
    u64t ac1[2][4], ac2[2][4];
#pragma unroll
    for (int i = 0; i < 2; i++)
#pragma unroll
        for (int j = 0; j < 4; j++) { ac1[i][j] = 0ull; ac2[i][j] = 0ull; }

    const float* Wh = W + (size_t)h * ND * NIN;

    for (int kb = 0; kb < NIN; kb += 32) {
        __syncthreads();
#pragma unroll
        for (int r = 0; r < 8; r++) {
            int idx = tid + r * 256;
            int k = idx & 31, m = idx >> 5;
            Xt[k][m] = x[(size_t)(n0 + m) * 257 + 1 + kb + k];
        }
#pragma unroll
        for (int r = 0; r < 16; r++) {
            int idx = tid + r * 256;
            int k = idx & 31, o = idx >> 5;
            Wt[k][o] = Wh[(size_t)o * NIN + kb + k];
        }
        __syncthreads();

#pragma unroll
        for (int k = 0; k < 32; k++) {
            float4 a  = *(const float4*)&Xt[k][ty * 4];
            float4 b0 = *(const float4*)&Wt[k][tx * 8];
            float4 b1 = *(const float4*)&Wt[k][tx * 8 + 4];
            u64t ap[2] = {pk2(a.x, a.y), pk2(a.z, a.w)};
            u64t bp[4] = {pk2(b0.x, b0.y), pk2(b0.z, b0.w),
                          pk2(b1.x, b1.y), pk2(b1.z, b1.w)};
            u64t bs[4] = {pk2(b0.y, b0.x), pk2(b0.w, b0.z),
                          pk2(b1.y, b1.x), pk2(b1.w, b1.z)};
#pragma unroll
            for (int i = 0; i < 2; i++)
#pragma unroll
                for (int j = 0; j < 4; j++) {
                    fma2(ac1[i][j], ap[i], bp[j]);
                    fma2(ac2[i][j], ap[i], bs[j]);
                }
        }
    }

    // unpack diagonals: rows (2i,2i+1), cols (2j,2j+1)
    float acc[4][8];
#pragma unroll
    for (int i = 0; i < 2; i++)
#pragma unroll
        for (int j = 0; j < 4; j++) {
            upk2(ac1[i][j], acc[2 * i][2 * j],     acc[2 * i + 1][2 * j + 1]);
            upk2(ac2[i][j], acc[2 * i][2 * j + 1], acc[2 * i + 1][2 * j]);
        }

    float bb[8];
#pragma unroll
    for (int j = 0; j < 8; j++) bb[j] = B[h * ND + tx * 8 + j];

    float ss[4] = {0.f, 0.f, 0.f, 0.f};
#pragma unroll
    for (int i = 0; i < 4; i++)
#pragma unroll
        for (int j = 0; j < 8; j++) {
            acc[i][j] += bb[j];
            ss[i] = fmaf(acc[i][j], acc[i][j], ss[i]);
        }

#pragma unroll
    for (int off = 8; off; off >>= 1)
#pragma unroll
        for (int i = 0; i < 4; i++)
            ss[i] += __shfl_xor_sync(0xffffffffu, ss[i], off);

#pragma unroll
    for (int i = 0; i < 4; i++) {
        int n = n0 + ty * 4 + i;
        float* dst = outS + ((size_t)(h * NN + n)) * ND + tx * 8;
        float4 w0 = {acc[i][0], acc[i][1], acc[i][2], acc[i][3]};
        float4 w1 = {acc[i][4], acc[i][5], acc[i][6], acc[i][7]};
        *(float4*)(dst)     = w0;
        *(float4*)(dst + 4) = w1;
        if (tx == 0) outT[h * NN + n] = sqrtf(ss[i] + 1.0f);
    }
}

// =====================================================================
// Kernel 2: flash attention + midpoint_norm — 128-row Q tile, 8x8 PV
// fragments, diagonal-packed FFMA2, alpha folded into Q.
// =====================================================================
#define QT_STR 132
#define KT_STR 68
#define PM_STR 70
#define VS_STR 128

#define OFF_QT 0
#define OFF_KT (129 * QT_STR)                 // 17028
#define OFF_PM (OFF_KT + 129 * KT_STR)        // 25800
#define OFF_VS (OFF_PM + 128 * PM_STR)        // 34760
#define OFF_VT (OFF_VS + 64 * VS_STR)         // 42952
#define ATTN_SMEM_FLOATS (OFF_VT + 64)        // 43016
#define ATTN_SMEM_BYTES  (ATTN_SMEM_FLOATS * 4)

__global__ __launch_bounds__(256, 1) void attn_kernel(const float* __restrict__ scale_ptr)
{
    extern __shared__ float sm[];
    float* Qt = sm + OFF_QT;   // [129][132]  row 0 = -alpha*t_q
    float* Kt = sm + OFF_KT;   // [129][68]   row 0 = +t_k
    float* Pm = sm + OFF_PM;   // [128][70]
    float* Vs = sm + OFF_VS;   // [64][128]
    float* vt = sm + OFF_VT;   // [64]

    const int h   = blockIdx.y;
    const int m0  = blockIdx.x * 128;
    const int tid = threadIdx.x;
    const int tx  = tid & 15;              // score cols tx*4.., PV cols tx*8..
    const int ty  = tid >> 4;              // rows ty*8..ty*8+7

    const float alpha = 2.0f / scale_ptr[0];

    // load Q tile transposed, scaled by alpha, sign-folded time in row 0
    for (int idx = tid; idx < 128 * 129; idx += 256) {
        int m = idx / 129;
        int d = idx - m * 129;
        float v = (d == 0) ? -g_QT[h * NN + m0 + m]
                           :  g_QS[((size_t)(h * NN + m0 + m)) * ND + d - 1];
        Qt[d * QT_STR + m] = v * alpha;
    }

    float m_i[8], l_i[8], acc_t[8];
    u64t ac1[4][4], ac2[4][4];             // PV accumulators (rows 8 x cols 8 diag-packed)
#pragma unroll
    for (int i = 0; i < 8; i++) { m_i[i] = -INFINITY; l_i[i] = 0.f; acc_t[i] = 0.f; }
#pragma unroll
    for (int i = 0; i < 4; i++)
#pragma unroll
        for (int j = 0; j < 4; j++) { ac1[i][j] = 0ull; ac2[i][j] = 0ull; }

    for (int k0 = 0; k0 < NN; k0 += 64) {
        __syncthreads();   // prev PV done before overwriting K/V
        for (int idx = tid; idx < 64 * 129; idx += 256) {
            int n = idx / 129;
            int d = idx - n * 129;
            float v = (d == 0) ? g_KT[h * NN + k0 + n]
                               : g_KS[((size_t)(h * NN + k0 + n)) * ND + d - 1];
            Kt[d * KT_STR + n] = v;
        }
#pragma unroll
        for (int r = 0; r < 8; r++) {
            int idx = tid + r * 256;
            int n  = idx >> 5;
            int d4 = (idx & 31) * 4;
            *(float4*)&Vs[n * VS_STR + d4] =
                *(const float4*)&g_VS[((size_t)(h * NN + k0 + n)) * ND + d4];
        }
        if (tid < 64) vt[tid] = g_VT[h * NN + k0 + tid];
        __syncthreads();

        // ---- scores: 8 rows x 4 cols, diagonal-packed ----
        u64t sd1[4][2], sd2[4][2];
#pragma unroll
        for (int i = 0; i < 4; i++) { sd1[i][0] = sd1[i][1] = 0ull; sd2[i][0] = sd2[i][1] = 0ull; }

        const float* qp = Qt + ty * 8;
        const float* kp = Kt + tx * 4;
        for (int d = 0; d < 129; d++) {
            float4 q0 = *(const float4*)qp;
            float4 q1 = *(const float4*)(qp + 4);
            qp += QT_STR;
            float4 kk = *(const float4*)kp;
            kp += KT_STR;
            u64t a0 = pk2(q0.x, q0.y), a1 = pk2(q0.z, q0.w);
            u64t a2 = pk2(q1.x, q1.y), a3 = pk2(q1.z, q1.w);
            u64t b0 = pk2(kk.x, kk.y), b0s = pk2(kk.y, kk.x);
            u64t b1 = pk2(kk.z, kk.w), b1s = pk2(kk.w, kk.z);
            fma2(sd1[0][0], a0, b0);  fma2(sd2[0][0], a0, b0s);
            fma2(sd1[0][1], a0, b1);  fma2(sd2[0][1], a0, b1s);
            fma2(sd1[1][0], a1, b0);  fma2(sd2[1][0], a1, b0s);
            fma2(sd1[1][1], a1, b1);  fma2(sd2[1][1], a1, b1s);
            fma2(sd1[2][0], a2, b0);  fma2(sd2[2][0], a2, b0s);
            fma2(sd1[2][1], a2, b1);  fma2(sd2[2][1], a2, b1s);
            fma2(sd1[3][0], a3, b0);  fma2(sd2[3][0], a3, b0s);
            fma2(sd1[3][1], a3, b1);  fma2(sd2[3][1], a3, b1s);
        }

        float s[8][4];
#pragma unroll
        for (int i2 = 0; i2 < 4; i2++)
#pragma unroll
            for (int j2 = 0; j2 < 2; j2++) {
                upk2(sd1[i2][j2], s[2 * i2][2 * j2],     s[2 * i2 + 1][2 * j2 + 1]);
                upk2(sd2[i2][j2], s[2 * i2][2 * j2 + 1], s[2 * i2 + 1][2 * j2]);
            }

        // ---- online softmax over 8 rows ----
        float tmax[8];
#pragma unroll
        for (int i = 0; i < 8; i++)
            tmax[i] = fmaxf(fmaxf(s[i][0], s[i][1]), fmaxf(s[i][2], s[i][3]));
#pragma unroll
        for (int off = 8; off; off >>= 1)
#pragma unroll
            for (int i = 0; i < 8; i++)
                tmax[i] = fmaxf(tmax[i], __shfl_xor_sync(0xffffffffu, tmax[i], off));

        float fac[8], tsum[8];
#pragma unroll
        for (int i = 0; i < 8; i++) {
            float newm = fmaxf(m_i[i], tmax[i]);
            fac[i] = __expf(m_i[i] - newm);
            m_i[i] = newm;
            tsum[i] = 0.f;
#pragma unroll
            for (int j = 0; j < 4; j++) {
                s[i][j] = __expf(s[i][j] - newm);
                tsum[i] += s[i][j];
            }
        }
#pragma unroll
        for (int off = 8; off; off >>= 1)
#pragma unroll
            for (int i = 0; i < 8; i++)
                tsum[i] += __shfl_xor_sync(0xffffffffu, tsum[i], off);

#pragma unroll
        for (int i = 0; i < 8; i++) {
            l_i[i] = l_i[i] * fac[i] + tsum[i];
            acc_t[i] *= fac[i];
        }
#pragma unroll
        for (int i2 = 0; i2 < 4; i2++) {
            u64t fp = pk2(fac[2 * i2], fac[2 * i2 + 1]);
#pragma unroll
            for (int j = 0; j < 4; j++) { mul2(ac1[i2][j], fp); mul2(ac2[i2][j], fp); }
        }

        // stage P tile (STS.64 pairs; stride 70 keeps PV scalar reads conflict-free)
#pragma unroll
        for (int i = 0; i < 8; i++) {
            float* pr = Pm + (ty * 8 + i) * PM_STR + tx * 4;
            *(float2*)(pr)     = make_float2(s[i][0], s[i][1]);
            *(float2*)(pr + 2) = make_float2(s[i][2], s[i][3]);
        }
        __syncthreads();

        // ---- PV: 8 rows x 8 cols diagonal-packed ----
#pragma unroll 4
        for (int k = 0; k < 64; k++) {
            float p[8];
#pragma unroll
            for (int i = 0; i < 8; i++) p[i] = Pm[(ty * 8 + i) * PM_STR + k];
            float4 v0 = *(const float4*)&Vs[k * VS_STR + tx * 8];
            float4 v1 = *(const float4*)&Vs[k * VS_STR + tx * 8 + 4];
            u64t vp[4] = {pk2(v0.x, v0.y), pk2(v0.z, v0.w),
                          pk2(v1.x, v1.y), pk2(v1.z, v1.w)};
            u64t vs_[4] = {pk2(v0.y, v0.x), pk2(v0.w, v0.z),
                           pk2(v1.y, v1.x), pk2(v1.w, v1.z)};
#pragma unroll
            for (int i2 = 0; i2 < 4; i2++) {
                u64t pp = pk2(p[2 * i2], p[2 * i2 + 1]);
#pragma unroll
                for (int j = 0; j < 4; j++) {
                    fma2(ac1[i2][j], pp, vp[j]);
                    fma2(ac2[i2][j], pp, vs_[j]);
                }
            }
            if (tx == 0) {
                float vv = vt[k];
#pragma unroll
                for (int i = 0; i < 8; i++) acc_t[i] = fmaf(p[i], vv, acc_t[i]);
            }
        }
    }

    // ---- epilogue: unpack, ave = acc/l, midpoint_norm, store ----
    float o[8][8];
#pragma unroll
    for (int i2 = 0; i2 < 4; i2++)
#pragma unroll
        for (int j2 = 0; j2 < 4; j2++) {
            upk2(ac1[i2][j2], o[2 * i2][2 * j2],     o[2 * i2 + 1][2 * j2 + 1]);
            upk2(ac2[i2][j2], o[2 * i2][2 * j2 + 1], o[2 * i2 + 1][2 * j2]);
        }

    float ssum[8];
#pragma unroll
    for (int i = 0; i < 8; i++) {
        float rl = 1.0f / l_i[i];
        ssum[i] = 0.f;
#pragma unroll
        for (int j = 0; j < 8; j++) {
            o[i][j] *= rl;
            ssum[i] = fmaf(o[i][j], o[i][j], ssum[i]);
        }
        acc_t[i] *= rl;
    }
#pragma unroll
    for (int off = 8; off; off >>= 1)
#pragma unroll
        for (int i = 0; i < 8; i++)
            ssum[i] += __shfl_xor_sync(0xffffffffu, ssum[i], off);

    const int src = (tid & 31) & 16;
#pragma unroll
    for (int i = 0; i < 8; i++) {
        float inner = ssum[i] - acc_t[i] * acc_t[i];
        float f = 1.0f / sqrtf(fmaxf(fabsf(inner), 1e-8f));
        f = __shfl_sync(0xffffffffu, f, src, 32);
        int n = m0 + ty * 8 + i;
        float* dst = g_OS + ((size_t)(h * NN + n)) * ND + tx * 8;
        float4 w0 = {o[i][0] * f, o[i][1] * f, o[i][2] * f, o[i][3] * f};
        float4 w1 = {o[i][4] * f, o[i][5] * f, o[i][6] * f, o[i][7] * f};
        *(float4*)(dst)     = w0;
        *(float4*)(dst + 4) = w1;
        if (tx == 0) g_OT[h * NN + n] = acc_t[i] * f;
    }
}

// =====================================================================
// Kernel 3: head mean + final midpoint_norm -> out[n][129]
// =====================================================================
__global__ __launch_bounds__(256) void final_kernel(float* __restrict__ out)
{
    const int warp = threadIdx.x >> 5;
    const int lane = threadIdx.x & 31;
    const int n = blockIdx.x * 8 + warp;

    float s0 = 0.f, s1 = 0.f, s2 = 0.f, s3 = 0.f, t = 0.f;
#pragma unroll
    for (int h = 0; h < NH; h++) {
        float4 v = *(const float4*)&g_OS[((size_t)(h * NN + n)) * ND + lane * 4];
        s0 += v.x; s1 += v.y; s2 += v.z; s3 += v.w;
        t += g_OT[h * NN + n];
    }
    const float inv = 1.0f / (float)NH;
    s0 *= inv; s1 *= inv; s2 *= inv; s3 *= inv; t *= inv;

    float q = s0 * s0 + s1 * s1 + s2 * s2 + s3 * s3;
#pragma unroll
    for (int off = 16; off; off >>= 1) q += __shfl_xor_sync(0xffffffffu, q, off);

    float inner = q - t * t;
    float f = 1.0f / sqrtf(fmaxf(fabsf(inner), 1e-8f));

    float* o = out + (size_t)n * 129;
    if (lane == 0) o[0] = t * f;
    o[1 + lane * 4 + 0] = s0 * f;
    o[1 + lane * 4 + 1] = s1 * f;
    o[1 + lane * 4 + 2] = s2 * f;
    o[1 + lane * 4 + 3] = s3 * f;
}

// =====================================================================
extern "C" void kernel_launch(void* const* d_in, const int* in_sizes, int n_in,
                              void* d_out, int out_size)
{
    const float* x     = (const float*)d_in[0];
    const float* Wq    = (const float*)d_in[1];
    const float* bq    = (const float*)d_in[2];
    const float* Wk    = (const float*)d_in[3];
    const float* bk    = (const float*)d_in[4];
    const float* Wv    = (const float*)d_in[5];
    const float* bv    = (const float*)d_in[6];
    const float* scale = (const float*)d_in[7];
    float* out = (float*)d_out;

    cudaFuncSetAttribute(attn_kernel,
                         cudaFuncAttributeMaxDynamicSharedMemorySize,
                         ATTN_SMEM_BYTES);

    proj_kernel<<<dim3(NN / 64, NH * 3), 256>>>(x, Wq, bq, Wk, bk, Wv, bv);
    attn_kernel<<<dim3(NN / 128, NH), 256, ATTN_SMEM_BYTES>>>(scale);
    final_kernel<<<NN / 8, 256>>>(out);
}

// round 5
// speedup vs baseline: 1.3095x; 1.3095x over previous
#include <cuda_runtime.h>
#include <math.h>

#define NH   12
#define NN   4096
#define ND   128
#define NIN  256

typedef unsigned long long u64t;

// ---- packed f32x2 helpers ----
__device__ __forceinline__ u64t pk2(float lo, float hi) {
    u64t r;
    asm("mov.b64 %0, {%1, %2};" : "=l"(r) : "f"(lo), "f"(hi));
    return r;
}
__device__ __forceinline__ void upk2(u64t v, float& lo, float& hi) {
    asm("mov.b64 {%0, %1}, %2;" : "=f"(lo), "=f"(hi) : "l"(v));
}
__device__ __forceinline__ void fma2(u64t& d, u64t a, u64t b) {
    asm("fma.rn.f32x2 %0, %1, %2, %0;" : "+l"(d) : "l"(a), "l"(b));
}
__device__ __forceinline__ void mul2(u64t& d, u64t a) {
    asm("mul.rn.f32x2 %0, %0, %1;" : "+l"(d) : "l"(a));
}

// ---- cp.async helpers ----
__device__ __forceinline__ void cpa16(void* dst, const void* src) {
    unsigned d = (unsigned)__cvta_generic_to_shared(dst);
    asm volatile("cp.async.cg.shared.global [%0], [%1], 16;" :: "r"(d), "l"(src));
}
__device__ __forceinline__ void cpa_commit() {
    asm volatile("cp.async.commit_group;" ::: "memory");
}
template<int N>
__device__ __forceinline__ void cpa_wait() {
    asm volatile("cp.async.wait_group %0;" :: "n"(N) : "memory");
}

// ---------------- scratch ----------------
__device__ float g_QTr[NH * 129 * NN];   // d-major, row0 = -alpha*t_q, rest alpha*s
__device__ float g_KTr[NH * 129 * NN];   // d-major, row0 = +t_k
__device__ float g_VS [NH * NN * ND];
__device__ float g_VT [NH * NN];
__device__ float g_OS [NH * NN * ND];
__device__ float g_OT [NH * NN];

// =====================================================================
// Kernel 1: projections. Q/K written d-major transposed (t in row 0,
// alpha + Minkowski sign folded into Q). V row-major as before.
// =====================================================================
__global__ __launch_bounds__(256) void proj_kernel(
    const float* __restrict__ x,
    const float* __restrict__ Wq, const float* __restrict__ bq,
    const float* __restrict__ Wk, const float* __restrict__ bk,
    const float* __restrict__ Wv, const float* __restrict__ bv,
    const float* __restrict__ scale_ptr)
{
    const int by  = blockIdx.y;
    const int h   = by % NH;
    const int sel = by / NH;

    const float* W = (sel == 0) ? Wq : (sel == 1) ? Wk : Wv;
    const float* B = (sel == 0) ? bq : (sel == 1) ? bk : bv;

    const int n0  = blockIdx.x * 64;
    const int tid = threadIdx.x;
    const int tx  = tid & 15;
    const int ty  = tid >> 4;

    __shared__ float Xt[32][68];
    __shared__ float Wt[32][132];

    u64t ac1[2][4], ac2[2][4];
#pragma unroll
    for (int i = 0; i < 2; i++)
#pragma unroll
        for (int j = 0; j < 4; j++) { ac1[i][j] = 0ull; ac2[i][j] = 0ull; }

    const float* Wh = W + (size_t)h * ND * NIN;

    for (int kb = 0; kb < NIN; kb += 32) {
        __syncthreads();
#pragma unroll
        for (int r = 0; r < 8; r++) {
            int idx = tid + r * 256;
            int k = idx & 31, m = idx >> 5;
            Xt[k][m] = x[(size_t)(n0 + m) * 257 + 1 + kb + k];
        }
#pragma unroll
        for (int r = 0; r < 16; r++) {
            int idx = tid + r * 256;
            int k = idx & 31, o = idx >> 5;
            Wt[k][o] = Wh[(size_t)o * NIN + kb + k];
        }
        __syncthreads();

#pragma unroll
        for (int k = 0; k < 32; k++) {
            float4 a  = *(const float4*)&Xt[k][ty * 4];
            float4 b0 = *(const float4*)&Wt[k][tx * 8];
            float4 b1 = *(const float4*)&Wt[k][tx * 8 + 4];
            u64t ap[2] = {pk2(a.x, a.y), pk2(a.z, a.w)};
            u64t bp[4] = {pk2(b0.x, b0.y), pk2(b0.z, b0.w),
                          pk2(b1.x, b1.y), pk2(b1.z, b1.w)};
            u64t bs[4] = {pk2(b0.y, b0.x), pk2(b0.w, b0.z),
                          pk2(b1.y, b1.x), pk2(b1.w, b1.z)};
#pragma unroll
            for (int i = 0; i < 2; i++)
#pragma unroll
                for (int j = 0; j < 4; j++) {
                    fma2(ac1[i][j], ap[i], bp[j]);
                    fma2(ac2[i][j], ap[i], bs[j]);
                }
        }
    }

    float acc[4][8];
#pragma unroll
    for (int i = 0; i < 2; i++)
#pragma unroll
        for (int j = 0; j < 4; j++) {
            upk2(ac1[i][j], acc[2 * i][2 * j],     acc[2 * i + 1][2 * j + 1]);
            upk2(ac2[i][j], acc[2 * i][2 * j + 1], acc[2 * i + 1][2 * j]);
        }

    float bb[8];
#pragma unroll
    for (int j = 0; j < 8; j++) bb[j] = B[h * ND + tx * 8 + j];

    float ss[4] = {0.f, 0.f, 0.f, 0.f};
#pragma unroll
    for (int i = 0; i < 4; i++)
#pragma unroll
        for (int j = 0; j < 8; j++) {
            acc[i][j] += bb[j];
            ss[i] = fmaf(acc[i][j], acc[i][j], ss[i]);
        }

#pragma unroll
    for (int off = 8; off; off >>= 1)
#pragma unroll
        for (int i = 0; i < 4; i++)
            ss[i] += __shfl_xor_sync(0xffffffffu, ss[i], off);

    const float alpha = 2.0f / scale_ptr[0];

    if (sel < 2) {
        // transposed d-major output with t in row 0
        const float smul = (sel == 0) ? alpha : 1.0f;
        const float tmul = (sel == 0) ? -alpha : 1.0f;
        float* T = ((sel == 0) ? g_QTr : g_KTr) + (size_t)h * 129 * NN;
#pragma unroll
        for (int j = 0; j < 8; j++) {
            int d = tx * 8 + j + 1;
            float4 w = {acc[0][j] * smul, acc[1][j] * smul,
                        acc[2][j] * smul, acc[3][j] * smul};
            *(float4*)&T[(size_t)d * NN + n0 + ty * 4] = w;
        }
        if (tx == 0) {
#pragma unroll
            for (int i = 0; i < 4; i++)
                T[n0 + ty * 4 + i] = tmul * sqrtf(ss[i] + 1.0f);
        }
    } else {
        // V: row-major
#pragma unroll
        for (int i = 0; i < 4; i++) {
            int n = n0 + ty * 4 + i;
            float* dst = g_VS + ((size_t)(h * NN + n)) * ND + tx * 8;
            float4 w0 = {acc[i][0], acc[i][1], acc[i][2], acc[i][3]};
            float4 w1 = {acc[i][4], acc[i][5], acc[i][6], acc[i][7]};
            *(float4*)(dst)     = w0;
            *(float4*)(dst + 4) = w1;
            if (tx == 0) g_VT[h * NN + n] = sqrtf(ss[i] + 1.0f);
        }
    }
}

// =====================================================================
// Kernel 2: flash attention + midpoint_norm.
// 512 threads, Q-tile 128 rows, cp.async double-buffered K, pipelined V.
// =====================================================================
#define QT_STR 132
#define KT_STR 68
#define PM_STR 132
#define VS_STR 128

#define OFF_QT  0
#define SZ_QT   (129 * QT_STR)            // 17028
#define OFF_KT0 (SZ_QT)
#define SZ_KT   (129 * KT_STR)            // 8772
#define OFF_KT1 (OFF_KT0 + SZ_KT)
#define OFF_VS  (OFF_KT1 + SZ_KT)         // 34572
#define OFF_PM  (OFF_VS + 64 * VS_STR)    // 42764
#define OFF_VT  (OFF_PM + 64 * PM_STR)    // 51212
#define ATTN_SMEM_FLOATS (OFF_VT + 64)    // 51276
#define ATTN_SMEM_BYTES  (ATTN_SMEM_FLOATS * 4)

__device__ __forceinline__ void load_k_tile(const float* __restrict__ src,
                                            float* __restrict__ dst, int tid)
{
    // 129 rows x 64 floats = 2064 float4
    for (int idx = tid; idx < 129 * 16; idx += 512) {
        int d = idx >> 4, c = idx & 15;
        cpa16(dst + d * KT_STR + c * 4, src + (size_t)d * NN + c * 4);
    }
}

__global__ __launch_bounds__(512, 1) void attn_kernel()
{
    extern __shared__ float sm[];
    float* Qt  = sm + OFF_QT;    // [129][132]
    float* Kt0 = sm + OFF_KT0;   // [129][68] x2
    float* Kt1 = sm + OFF_KT1;
    float* Vs  = sm + OFF_VS;    // [64][128]
    float* Pm  = sm + OFF_PM;    // [64][132]  (k-major)
    float* vt  = sm + OFF_VT;    // [64]

    const int h   = blockIdx.y;
    const int m0  = blockIdx.x * 128;
    const int tid = threadIdx.x;
    const int tx  = tid & 15;    // score cols tx*4.. / PV cols tx*8..
    const int ty  = tid >> 4;    // rows ty*4..ty*4+3

    const float* qsrc = g_QTr + (size_t)h * 129 * NN + m0;
    const float* kbase = g_KTr + (size_t)h * 129 * NN;

    // prologue: Qt + K(0)  (one commit group)
    for (int idx = tid; idx < 129 * 32; idx += 512) {
        int d = idx >> 5, c = idx & 31;
        cpa16(Qt + d * QT_STR + c * 4, qsrc + (size_t)d * NN + c * 4);
    }
    load_k_tile(kbase, Kt0, tid);
    cpa_commit();

    float m_i[4], l_i[4], acc_t[4];
    u64t ac1[2][4], ac2[2][4];
#pragma unroll
    for (int i = 0; i < 4; i++) { m_i[i] = -INFINITY; l_i[i] = 0.f; acc_t[i] = 0.f; }
#pragma unroll
    for (int i = 0; i < 2; i++)
#pragma unroll
        for (int j = 0; j < 4; j++) { ac1[i][j] = 0ull; ac2[i][j] = 0ull; }

    for (int c64 = 0; c64 < 64; c64++) {
        const int k0 = c64 * 64;
        float* Ktc = (c64 & 1) ? Kt1 : Kt0;
        float* Ktn = (c64 & 1) ? Kt0 : Kt1;

        __syncthreads();   // A: PV(c-1)/Pm reads done; Vs reusable

        // V(c) + vt(c)
        {
            const float* vsrc = g_VS + ((size_t)(h * NN + k0)) * ND;
            for (int idx = tid; idx < 2048; idx += 512) {
                int n = idx >> 5, c = idx & 31;
                cpa16(Vs + n * VS_STR + c * 4, vsrc + (size_t)n * ND + c * 4);
            }
            if (tid < 16) cpa16(vt + tid * 4, g_VT + h * NN + k0 + tid * 4);
        }
        cpa_commit();                       // group V(c)

        if (c64 < 63) {
            load_k_tile(kbase + k0 + 64, Ktn, tid);
            cpa_commit();                   // group K(c+1)
            cpa_wait<2>();                  // K(c) [and Qt] complete
        } else {
            cpa_wait<1>();
        }
        __syncthreads();   // B: Kt(c) visible to all threads

        // ---- scores: 4x4 diag-packed over 129 dims ----
        u64t sd1[4], sd2[4];
#pragma unroll
        for (int i = 0; i < 4; i++) { sd1[i] = 0ull; sd2[i] = 0ull; }

        const float* qp = Qt + ty * 4;
        const float* kp = Ktc + tx * 4;
#pragma unroll 3
        for (int d = 0; d < 129; d++) {
            float4 q  = *(const float4*)qp; qp += QT_STR;
            float4 kk = *(const float4*)kp; kp += KT_STR;
            u64t a0 = pk2(q.x, q.y),  a1 = pk2(q.z, q.w);
            u64t b0 = pk2(kk.x, kk.y), b1 = pk2(kk.z, kk.w);
            u64t b0s = pk2(kk.y, kk.x), b1s = pk2(kk.w, kk.z);
            fma2(sd1[0], a0, b0);  fma2(sd2[0], a0, b0s);
            fma2(sd1[1], a0, b1);  fma2(sd2[1], a0, b1s);
            fma2(sd1[2], a1, b0);  fma2(sd2[2], a1, b0s);
            fma2(sd1[3], a1, b1);  fma2(sd2[3], a1, b1s);
        }

        float s[4][4];
#pragma unroll
        for (int i2 = 0; i2 < 2; i2++)
#pragma unroll
            for (int j2 = 0; j2 < 2; j2++) {
                upk2(sd1[i2 * 2 + j2], s[2 * i2][2 * j2],     s[2 * i2 + 1][2 * j2 + 1]);
                upk2(sd2[i2 * 2 + j2], s[2 * i2][2 * j2 + 1], s[2 * i2 + 1][2 * j2]);
            }

        // ---- online softmax ----
        float tmax[4];
#pragma unroll
        for (int i = 0; i < 4; i++)
            tmax[i] = fmaxf(fmaxf(s[i][0], s[i][1]), fmaxf(s[i][2], s[i][3]));
#pragma unroll
        for (int off = 8; off; off >>= 1)
#pragma unroll
            for (int i = 0; i < 4; i++)
                tmax[i] = fmaxf(tmax[i], __shfl_xor_sync(0xffffffffu, tmax[i], off));

        float fac[4], tsum[4];
#pragma unroll
        for (int i = 0; i < 4; i++) {
            float newm = fmaxf(m_i[i], tmax[i]);
            fac[i] = __expf(m_i[i] - newm);
            m_i[i] = newm;
            tsum[i] = 0.f;
#pragma unroll
            for (int j = 0; j < 4; j++) {
                s[i][j] = __expf(s[i][j] - newm);
                tsum[i] += s[i][j];
            }
        }
#pragma unroll
        for (int off = 8; off; off >>= 1)
#pragma unroll
            for (int i = 0; i < 4; i++)
                tsum[i] += __shfl_xor_sync(0xffffffffu, tsum[i], off);

#pragma unroll
        for (int i = 0; i < 4; i++) {
            l_i[i] = l_i[i] * fac[i] + tsum[i];
            acc_t[i] *= fac[i];
        }
#pragma unroll
        for (int i2 = 0; i2 < 2; i2++) {
            u64t fp = pk2(fac[2 * i2], fac[2 * i2 + 1]);
#pragma unroll
            for (int j = 0; j < 4; j++) { mul2(ac1[i2][j], fp); mul2(ac2[i2][j], fp); }
        }

        // stage P tile (k-major)
#pragma unroll
        for (int j = 0; j < 4; j++) {
            float4 w = {s[0][j], s[1][j], s[2][j], s[3][j]};
            *(float4*)(Pm + (tx * 4 + j) * PM_STR + ty * 4) = w;
        }

        if (c64 < 63) cpa_wait<1>(); else cpa_wait<0>();   // V(c) complete
        __syncthreads();   // C: Pm + Vs visible

        // ---- PV: 4 rows x 8 cols diag-packed ----
#pragma unroll 4
        for (int k = 0; k < 64; k++) {
            float4 p  = *(const float4*)(Pm + k * PM_STR + ty * 4);
            const float* vrow = Vs + k * VS_STR + tx * 8;
            float4 v0 = *(const float4*)(vrow);
            float4 v1 = *(const float4*)(vrow + 4);
            u64t pp0 = pk2(p.x, p.y), pp1 = pk2(p.z, p.w);
            u64t vp0 = pk2(v0.x, v0.y), vp1 = pk2(v0.z, v0.w);
            u64t vp2 = pk2(v1.x, v1.y), vp3 = pk2(v1.z, v1.w);
            u64t vq0 = pk2(v0.y, v0.x), vq1 = pk2(v0.w, v0.z);
            u64t vq2 = pk2(v1.y, v1.x), vq3 = pk2(v1.w, v1.z);
            fma2(ac1[0][0], pp0, vp0);  fma2(ac2[0][0], pp0, vq0);
            fma2(ac1[0][1], pp0, vp1);  fma2(ac2[0][1], pp0, vq1);
            fma2(ac1[0][2], pp0, vp2);  fma2(ac2[0][2], pp0, vq2);
            fma2(ac1[0][3], pp0, vp3);  fma2(ac2[0][3], pp0, vq3);
            fma2(ac1[1][0], pp1, vp0);  fma2(ac2[1][0], pp1, vq0);
            fma2(ac1[1][1], pp1, vp1);  fma2(ac2[1][1], pp1, vq1);
            fma2(ac1[1][2], pp1, vp2);  fma2(ac2[1][2], pp1, vq2);
            fma2(ac1[1][3], pp1, vp3);  fma2(ac2[1][3], pp1, vq3);
        }

        // distributed t-accumulation: lane handles k = tx*4..tx*4+3
#pragma unroll
        for (int j = 0; j < 4; j++) {
            int k = tx * 4 + j;
            float vv = vt[k];
            float4 p = *(const float4*)(Pm + k * PM_STR + ty * 4);
            acc_t[0] = fmaf(p.x, vv, acc_t[0]);
            acc_t[1] = fmaf(p.y, vv, acc_t[1]);
            acc_t[2] = fmaf(p.z, vv, acc_t[2]);
            acc_t[3] = fmaf(p.w, vv, acc_t[3]);
        }
    }

    // ---- epilogue ----
    float o[4][8];
#pragma unroll
    for (int i2 = 0; i2 < 2; i2++)
#pragma unroll
        for (int j = 0; j < 4; j++) {
            upk2(ac1[i2][j], o[2 * i2][2 * j],     o[2 * i2 + 1][2 * j + 1]);
            upk2(ac2[i2][j], o[2 * i2][2 * j + 1], o[2 * i2 + 1][2 * j]);
        }

    float ssum[4];
#pragma unroll
    for (int i = 0; i < 4; i++) {
        float rl = 1.0f / l_i[i];
        ssum[i] = 0.f;
#pragma unroll
        for (int j = 0; j < 8; j++) {
            o[i][j] *= rl;
            ssum[i] = fmaf(o[i][j], o[i][j], ssum[i]);
        }
        acc_t[i] *= rl;   // per-lane partial
    }
#pragma unroll
    for (int off = 8; off; off >>= 1)
#pragma unroll
        for (int i = 0; i < 4; i++) {
            ssum[i]  += __shfl_xor_sync(0xffffffffu, ssum[i], off);
            acc_t[i] += __shfl_xor_sync(0xffffffffu, acc_t[i], off);
        }

#pragma unroll
    for (int i = 0; i < 4; i++) {
        float inner = ssum[i] - acc_t[i] * acc_t[i];
        float f = 1.0f / sqrtf(fmaxf(fabsf(inner), 1e-8f));
        int n = m0 + ty * 4 + i;
        float* dst = g_OS + ((size_t)(h * NN + n)) * ND + tx * 8;
        float4 w0 = {o[i][0] * f, o[i][1] * f, o[i][2] * f, o[i][3] * f};
        float4 w1 = {o[i][4] * f, o[i][5] * f, o[i][6] * f, o[i][7] * f};
        *(float4*)(dst)     = w0;
        *(float4*)(dst + 4) = w1;
        if (tx == 0) g_OT[h * NN + n] = acc_t[i] * f;
    }
}

// =====================================================================
// Kernel 3: head mean + final midpoint_norm -> out[n][129]
// =====================================================================
__global__ __launch_bounds__(256) void final_kernel(float* __restrict__ out)
{
    const int warp = threadIdx.x >> 5;
    const int lane = threadIdx.x & 31;
    const int n = blockIdx.x * 8 + warp;

    float s0 = 0.f, s1 = 0.f, s2 = 0.f, s3 = 0.f, t = 0.f;
#pragma unroll
    for (int h = 0; h < NH; h++) {
        float4 v = *(const float4*)&g_OS[((size_t)(h * NN + n)) * ND + lane * 4];
        s0 += v.x; s1 += v.y; s2 += v.z; s3 += v.w;
        t += g_OT[h * NN + n];
    }
    const float inv = 1.0f / (float)NH;
    s0 *= inv; s1 *= inv; s2 *= inv; s3 *= inv; t *= inv;

    float q = s0 * s0 + s1 * s1 + s2 * s2 + s3 * s3;
#pragma unroll
    for (int off = 16; off; off >>= 1) q += __shfl_xor_sync(0xffffffffu, q, off);

    float inner = q - t * t;
    float f = 1.0f / sqrtf(fmaxf(fabsf(inner), 1e-8f));

    float* o = out + (size_t)n * 129;
    if (lane == 0) o[0] = t * f;
    o[1 + lane * 4 + 0] = s0 * f;
    o[1 + lane * 4 + 1] = s1 * f;
    o[1 + lane * 4 + 2] = s2 * f;
    o[1 + lane * 4 + 3] = s3 * f;
}

// =====================================================================
extern "C" void kernel_launch(void* const* d_in, const int* in_sizes, int n_in,
                              void* d_out, int out_size)
{
    const float* x     = (const float*)d_in[0];
    const float* Wq    = (const float*)d_in[1];
    const float* bq    = (const float*)d_in[2];
    const float* Wk    = (const float*)d_in[3];
    const float* bk    = (const float*)d_in[4];
    const float* Wv    = (const float*)d_in[5];
    const float* bv    = (const float*)d_in[6];
    const float* scale = (const float*)d_in[7];
    float* out = (float*)d_out;

    cudaFuncSetAttribute(attn_kernel,
                         cudaFuncAttributeMaxDynamicSharedMemorySize,
                         ATTN_SMEM_BYTES);

    proj_kernel<<<dim3(NN / 64, NH * 3), 256>>>(x, Wq, bq, Wk, bk, Wv, bv, scale);
    attn_kernel<<<dim3(NN / 128, NH), 512, ATTN_SMEM_BYTES>>>();
    final_kernel<<<NN / 8, 256>>>(out);
}